// round 3
// baseline (speedup 1.0000x reference)
#include <cuda_runtime.h>
#include <cstdint>

#define B_  32
#define T_  2048
#define D_  256
#define H_  256
#define A_  18
#define G4  1024
#define M_  (B_*T_)          // 65536

#define LOGITS_OFF 0
#define LAST_OFF   ((size_t)M_*A_)                   // 1179648
#define C_OFF      (LAST_OFF + (size_t)M_*H_)        // 17956864
#define HF_OFF     (C_OFF + (size_t)B_*H_)           // 17965056

// 256 MB scratch for pre-computed input gates (x @ Wx + b)
__device__ float g_scr[(size_t)M_ * G4];

// ---------------- f32x2 packed helpers ----------------
__device__ __forceinline__ unsigned long long pk2(float lo, float hi){
    unsigned long long r;
    asm("mov.b64 %0, {%1,%2};" : "=l"(r) : "f"(lo), "f"(hi));
    return r;
}
__device__ __forceinline__ void fma2(unsigned long long &d, unsigned long long a, unsigned long long b){
    asm("fma.rn.f32x2 %0, %1, %2, %0;" : "+l"(d) : "l"(a), "l"(b));
}
__device__ __forceinline__ float2 up2(unsigned long long v){
    float2 f;
    asm("mov.b64 {%0,%1}, %2;" : "=f"(f.x), "=f"(f.y) : "l"(v));
    return f;
}

__device__ __forceinline__ float sigf(float x){
    return 1.0f / (1.0f + __expf(-x));
}

// ======================================================================
// Kernel 1: pre-GEMM  G[b*T+t][c] = x[b,t,:] @ W[0:256, c] + b[c]
// BM=128, BN=64, BK=16, 256 threads, thread tile 8x4 via f32x2
// ======================================================================
#define PG_BM 128
#define PG_BN 64
#define PG_BK 16

__global__ __launch_bounds__(256) void pregemm_k(
    const float* __restrict__ x, const float* __restrict__ W,
    const float* __restrict__ bias)
{
    __shared__ float a_s[PG_BK][PG_BM];
    __shared__ float b_s[PG_BK][PG_BN];

    int tid = threadIdx.x;
    int m0 = blockIdx.y * PG_BM;
    int n0 = blockIdx.x * PG_BN;
    int tx = tid & 15;           // 0..15 -> 4 cols each
    int ty = tid >> 4;           // 0..15 -> 8 rows each

    unsigned long long acc[8][2];
#pragma unroll
    for (int i = 0; i < 8; i++){ acc[i][0] = pk2(0.f,0.f); acc[i][1] = pk2(0.f,0.f); }

    for (int k0 = 0; k0 < D_; k0 += PG_BK){
        // load A tile: 128 rows x 16 k = 512 float4, 2 per thread
#pragma unroll
        for (int i = 0; i < 2; i++){
            int f4 = tid*2 + i;
            int m  = f4 >> 2;          // 4 float4 per row
            int kq = f4 & 3;
            float4 v = *(const float4*)&x[(size_t)(m0+m)*D_ + k0 + kq*4];
            a_s[kq*4+0][m] = v.x; a_s[kq*4+1][m] = v.y;
            a_s[kq*4+2][m] = v.z; a_s[kq*4+3][m] = v.w;
        }
        // load B tile: 16 rows x 64 cols = 256 float4, 1 per thread
        {
            int row = tid >> 4, cq = tid & 15;
            float4 v = *(const float4*)&W[(size_t)(k0+row)*G4 + n0 + cq*4];
            *(float4*)&b_s[row][cq*4] = v;
        }
        __syncthreads();
#pragma unroll
        for (int kk = 0; kk < PG_BK; kk++){
            float4 a0 = *(float4*)&a_s[kk][ty*8];
            float4 a1 = *(float4*)&a_s[kk][ty*8+4];
            float4 bb = *(float4*)&b_s[kk][tx*4];
            unsigned long long bp0 = pk2(bb.x, bb.y);
            unsigned long long bp1 = pk2(bb.z, bb.w);
            float ar[8] = {a0.x,a0.y,a0.z,a0.w,a1.x,a1.y,a1.z,a1.w};
#pragma unroll
            for (int i = 0; i < 8; i++){
                unsigned long long ap = pk2(ar[i], ar[i]);
                fma2(acc[i][0], ap, bp0);
                fma2(acc[i][1], ap, bp1);
            }
        }
        __syncthreads();
    }

    float4 bv = *(const float4*)&bias[n0 + tx*4];
#pragma unroll
    for (int i = 0; i < 8; i++){
        float2 lo = up2(acc[i][0]);
        float2 hi = up2(acc[i][1]);
        float4 outv = make_float4(lo.x + bv.x, lo.y + bv.y, hi.x + bv.z, hi.y + bv.w);
        *(float4*)&g_scr[(size_t)(m0 + ty*8 + i)*G4 + n0 + tx*4] = outv;
    }
}

// ======================================================================
// Kernel 2: recurrent LSTM.
// 16 clusters x 8 CTAs. Cluster = 2 batches. CTA = 32 hidden units
// (= 128 gate columns). 256 threads: (col 0..127) x (batch 0..1),
// warp = 16 cols x 2 batches for smem dedup.
// Weights: k<KR in registers, rest in smem. h exchanged via DSMEM.
// ======================================================================
#define KR    128
#define NCOL  128
#define WS_ST 132            // padded stride (floats) for smem weights

// smem float layout: w_s[128*132] | h_buf[2][2][256] | gate_s[2][128] | c_s[2][32]
#define SM_WS    0
#define SM_HBUF  (NCOL*WS_ST)
#define SM_GATE  (SM_HBUF + 2*2*256)
#define SM_CS    (SM_GATE + 2*NCOL)
#define SM_TOT   (SM_CS + 2*32)
#define SMEM_REC_BYTES (SM_TOT*4)

__device__ __forceinline__ void st_cluster_f32(uint32_t saddr, int rank, float v){
    uint32_t r;
    asm volatile("mapa.shared::cluster.u32 %0, %1, %2;" : "=r"(r) : "r"(saddr), "r"(rank));
    asm volatile("st.shared::cluster.f32 [%0], %1;" :: "r"(r), "f"(v) : "memory");
}
__device__ __forceinline__ void cluster_sync_(){
    asm volatile("barrier.cluster.arrive.aligned;" ::: "memory");
    asm volatile("barrier.cluster.wait.aligned;"   ::: "memory");
}

__global__ __launch_bounds__(256,1) __cluster_dims__(8,1,1)
void lstm_rec_k(const float* __restrict__ W, const int* __restrict__ seq_lens,
                const float* __restrict__ c_in, const float* __restrict__ h_in,
                float* __restrict__ out)
{
    extern __shared__ float sm[];
    float* w_s    = sm + SM_WS;
    float* h_buf  = sm + SM_HBUF;
    float* gate_s = sm + SM_GATE;
    float* c_s    = sm + SM_CS;

    int tid  = threadIdx.x;
    int rank = blockIdx.x & 7;
    int cl   = blockIdx.x >> 3;
    int bb   = (tid >> 4) & 1;
    int col  = (tid & 15) | ((tid >> 5) << 4);    // 0..127
    int bglob = cl*2 + bb;
    int gate = col >> 5, uu0 = col & 31;
    int gcol = gate*256 + rank*32 + uu0;          // global gate column

    const float* Wh = W + (size_t)D_*G4;          // h-part rows 256..511

    // --- one-time: weights into regs (k<KR) packed as f32x2 pairs ---
    unsigned long long wreg2[KR/2];
#pragma unroll
    for (int k2 = 0; k2 < KR/2; k2++){
        float w0 = Wh[(size_t)(2*k2  )*G4 + gcol];
        float w1 = Wh[(size_t)(2*k2+1)*G4 + gcol];
        wreg2[k2] = pk2(w0, w1);
    }
    // rest of weights into smem (only bb==0 threads store)
    if (bb == 0){
        for (int k = KR; k < H_; k++)
            w_s[col*WS_ST + (k - KR)] = Wh[(size_t)k*G4 + gcol];
    }
    // --- init h, c ---
    for (int k = col; k < H_; k += NCOL)
        h_buf[(0*2 + bb)*256 + k] = h_in[(size_t)bglob*H_ + k];
    int slen_u = 0;
    if (tid < 64){
        int b = tid >> 5, uu = tid & 31;
        c_s[b*32 + uu] = c_in[(size_t)(cl*2 + b)*H_ + rank*32 + uu];
        slen_u = seq_lens[cl*2 + b];
    }
    __syncthreads();
    cluster_sync_();

    int phase = 0;
    float pre = g_scr[((size_t)bglob*T_ + 0)*G4 + gcol];

    for (int t = 0; t < T_; t++){
        float pre_nxt = 0.f;
        if (t+1 < T_) pre_nxt = g_scr[((size_t)bglob*T_ + (t+1))*G4 + gcol];

        const float* hb = h_buf + (phase*2 + bb)*256;
        const ulonglong2* hb2 = (const ulonglong2*)hb;
        unsigned long long acc2 = pk2(pre, 0.f);
        // register-weight part
#pragma unroll
        for (int q = 0; q < KR/4; q++){
            ulonglong2 hp = hb2[q];
            fma2(acc2, wreg2[2*q  ], hp.x);
            fma2(acc2, wreg2[2*q+1], hp.y);
        }
        // smem-weight part
        const ulonglong2* w2 = (const ulonglong2*)(w_s + col*WS_ST);
#pragma unroll
        for (int q = 0; q < (H_-KR)/4; q++){
            ulonglong2 hp = hb2[KR/4 + q];
            ulonglong2 wp = w2[q];
            fma2(acc2, wp.x, hp.x);
            fma2(acc2, wp.y, hp.y);
        }
        float2 s = up2(acc2);
        gate_s[bb*NCOL + col] = s.x + s.y;
        __syncthreads();

        if (tid < 64){
            int b = tid >> 5, uu = tid & 31;
            float gi = gate_s[b*NCOL + uu];
            float gj = gate_s[b*NCOL + 32 + uu];
            float gf = gate_s[b*NCOL + 64 + uu];
            float go = gate_s[b*NCOL + 96 + uu];
            float c  = c_s[b*32 + uu];
            float nc = c * sigf(gf + 1.0f) + sigf(gi) * tanhf(gj);
            float nh = tanhf(nc) * sigf(go);
            bool mask = (t < slen_u);
            float h_old = h_buf[(phase*2 + b)*256 + rank*32 + uu];
            float cw = mask ? nc : c;
            float hw = mask ? nh : h_old;
            c_s[b*32 + uu] = cw;
            int bg = cl*2 + b;
            out[LAST_OFF + ((size_t)bg*T_ + t)*H_ + rank*32 + uu] = mask ? nh : 0.f;
            // broadcast new h to all cluster CTAs (phase^1 buffer)
            uint32_t sa = (uint32_t)__cvta_generic_to_shared(
                &h_buf[((phase^1)*2 + b)*256 + rank*32 + uu]);
#pragma unroll
            for (int r2 = 0; r2 < 8; r2++)
                st_cluster_f32(sa, r2, hw);
        }
        cluster_sync_();
        phase ^= 1;
        pre = pre_nxt;
    }

    if (tid < 64){
        int b = tid >> 5, uu = tid & 31;
        int bg = cl*2 + b;
        out[C_OFF  + (size_t)bg*H_ + rank*32 + uu] = c_s[b*32 + uu];
        out[HF_OFF + (size_t)bg*H_ + rank*32 + uu] =
            h_buf[(phase*2 + b)*256 + rank*32 + uu];
    }
}

// ======================================================================
// Kernel 3: logits = last_layer @ W_out + b_out   [65536,256]@[256,18]
// block = 14 rows x 18 outputs = 252 threads
// ======================================================================
#define WO_ST 260

__global__ __launch_bounds__(252) void logits_k(
    const float* __restrict__ Wout, const float* __restrict__ bout,
    float* __restrict__ out)
{
    __shared__ float wo[A_*WO_ST];
    __shared__ float bo[A_];
    int tid = threadIdx.x;
    for (int i = tid; i < H_*A_; i += 252){
        int k = i / A_, a = i % A_;
        wo[a*WO_ST + k] = Wout[(size_t)k*A_ + a];
    }
    if (tid < A_) bo[tid] = bout[tid];
    __syncthreads();

    int r = blockIdx.x*14 + tid/A_;
    int a = tid % A_;
    if (r >= M_) return;
    const float* hrow = out + LAST_OFF + (size_t)r*H_;
    const float* wa = wo + a*WO_ST;
    unsigned long long acc = pk2(0.f, 0.f);
#pragma unroll
    for (int k4 = 0; k4 < H_/4; k4++){
        float4 hv = *(const float4*)&hrow[k4*4];
        float4 wv = *(const float4*)&wa[k4*4];
        fma2(acc, pk2(hv.x,hv.y), pk2(wv.x,wv.y));
        fma2(acc, pk2(hv.z,hv.w), pk2(wv.z,wv.w));
    }
    float2 s = up2(acc);
    out[(size_t)r*A_ + a] = s.x + s.y + bo[a];
}

// ======================================================================
extern "C" void kernel_launch(void* const* d_in, const int* in_sizes, int n_in,
                              void* d_out, int out_size)
{
    const float* x     = (const float*)d_in[0];
    const int*   seq   = (const int*)  d_in[1];
    const float* c_in  = (const float*)d_in[2];
    const float* h_in  = (const float*)d_in[3];
    const float* W     = (const float*)d_in[4];
    const float* b     = (const float*)d_in[5];
    const float* Wout  = (const float*)d_in[6];
    const float* bout  = (const float*)d_in[7];
    float* out = (float*)d_out;

    cudaFuncSetAttribute(lstm_rec_k, cudaFuncAttributeMaxDynamicSharedMemorySize,
                         SMEM_REC_BYTES);

    pregemm_k<<<dim3(G4/PG_BN, M_/PG_BM), 256>>>(x, W, b);
    lstm_rec_k<<<128, 256, SMEM_REC_BYTES>>>(W, seq, c_in, h_in, out);
    logits_k<<<(M_ + 13)/14, 252>>>(Wout, bout, out);
}

// round 4
// speedup vs baseline: 1.0010x; 1.0010x over previous
#include <cuda_runtime.h>
#include <cstdint>

#define B_  32
#define T_  2048
#define D_  256
#define H_  256
#define A_  18
#define G4  1024
#define M_  (B_*T_)          // 65536

#define LOGITS_OFF 0
#define LAST_OFF   ((size_t)M_*A_)                   // 1179648
#define C_OFF      (LAST_OFF + (size_t)M_*H_)        // 17956864
#define HF_OFF     (C_OFF + (size_t)B_*H_)           // 17965056

// 256 MB scratch for pre-computed input gates (x @ Wx + b)
__device__ float g_scr[(size_t)M_ * G4];

// ---------------- f32x2 packed helpers ----------------
__device__ __forceinline__ unsigned long long pk2(float lo, float hi){
    unsigned long long r;
    asm("mov.b64 %0, {%1,%2};" : "=l"(r) : "f"(lo), "f"(hi));
    return r;
}
__device__ __forceinline__ void fma2(unsigned long long &d, unsigned long long a, unsigned long long b){
    asm("fma.rn.f32x2 %0, %1, %2, %0;" : "+l"(d) : "l"(a), "l"(b));
}
__device__ __forceinline__ float2 up2(unsigned long long v){
    float2 f;
    asm("mov.b64 {%0,%1}, %2;" : "=f"(f.x), "=f"(f.y) : "l"(v));
    return f;
}

__device__ __forceinline__ float sigf(float x){
    return 1.0f / (1.0f + __expf(-x));
}

// ======================================================================
// Kernel 1: pre-GEMM  G[b*T+t][c] = x[b,t,:] @ W[0:256, c] + b[c]
// BM=128, BN=64, BK=16, 256 threads, thread tile 8x4 via f32x2
// ======================================================================
#define PG_BM 128
#define PG_BN 64
#define PG_BK 16

__global__ __launch_bounds__(256) void pregemm_k(
    const float* __restrict__ x, const float* __restrict__ W,
    const float* __restrict__ bias)
{
    __shared__ float a_s[PG_BK][PG_BM];
    __shared__ float b_s[PG_BK][PG_BN];

    int tid = threadIdx.x;
    int m0 = blockIdx.y * PG_BM;
    int n0 = blockIdx.x * PG_BN;
    int tx = tid & 15;           // 0..15 -> 4 cols each
    int ty = tid >> 4;           // 0..15 -> 8 rows each

    unsigned long long acc[8][2];
#pragma unroll
    for (int i = 0; i < 8; i++){ acc[i][0] = pk2(0.f,0.f); acc[i][1] = pk2(0.f,0.f); }

    for (int k0 = 0; k0 < D_; k0 += PG_BK){
        // load A tile: 128 rows x 16 k = 512 float4, 2 per thread
#pragma unroll
        for (int i = 0; i < 2; i++){
            int f4 = tid*2 + i;
            int m  = f4 >> 2;          // 4 float4 per row
            int kq = f4 & 3;
            float4 v = *(const float4*)&x[(size_t)(m0+m)*D_ + k0 + kq*4];
            a_s[kq*4+0][m] = v.x; a_s[kq*4+1][m] = v.y;
            a_s[kq*4+2][m] = v.z; a_s[kq*4+3][m] = v.w;
        }
        // load B tile: 16 rows x 64 cols = 256 float4, 1 per thread
        {
            int row = tid >> 4, cq = tid & 15;
            float4 v = *(const float4*)&W[(size_t)(k0+row)*G4 + n0 + cq*4];
            *(float4*)&b_s[row][cq*4] = v;
        }
        __syncthreads();
#pragma unroll
        for (int kk = 0; kk < PG_BK; kk++){
            float4 a0 = *(float4*)&a_s[kk][ty*8];
            float4 a1 = *(float4*)&a_s[kk][ty*8+4];
            float4 bb = *(float4*)&b_s[kk][tx*4];
            unsigned long long bp0 = pk2(bb.x, bb.y);
            unsigned long long bp1 = pk2(bb.z, bb.w);
            float ar[8] = {a0.x,a0.y,a0.z,a0.w,a1.x,a1.y,a1.z,a1.w};
#pragma unroll
            for (int i = 0; i < 8; i++){
                unsigned long long ap = pk2(ar[i], ar[i]);
                fma2(acc[i][0], ap, bp0);
                fma2(acc[i][1], ap, bp1);
            }
        }
        __syncthreads();
    }

    float4 bv = *(const float4*)&bias[n0 + tx*4];
#pragma unroll
    for (int i = 0; i < 8; i++){
        float2 lo = up2(acc[i][0]);
        float2 hi = up2(acc[i][1]);
        float4 outv = make_float4(lo.x + bv.x, lo.y + bv.y, hi.x + bv.z, hi.y + bv.w);
        *(float4*)&g_scr[(size_t)(m0 + ty*8 + i)*G4 + n0 + tx*4] = outv;
    }
}

// ======================================================================
// Kernel 2: recurrent LSTM.
// 16 clusters x 8 CTAs. Cluster = 2 batches. CTA = 32 hidden units
// (= 128 gate columns). 256 threads: (col 0..127) x (batch 0..1),
// warp = 16 cols x 2 batches for smem dedup.
// Weights: k<KR in registers, rest in smem. h exchanged via DSMEM.
// ======================================================================
#define KR    128
#define NCOL  128
#define WS_ST 132            // padded stride (floats) for smem weights

// smem float layout: w_s[128*132] | h_buf[2][2][256] | gate_s[2][128] | c_s[2][32]
#define SM_WS    0
#define SM_HBUF  (NCOL*WS_ST)
#define SM_GATE  (SM_HBUF + 2*2*256)
#define SM_CS    (SM_GATE + 2*NCOL)
#define SM_TOT   (SM_CS + 2*32)
#define SMEM_REC_BYTES (SM_TOT*4)

__device__ __forceinline__ void st_cluster_f32(uint32_t saddr, int rank, float v){
    uint32_t r;
    asm volatile("mapa.shared::cluster.u32 %0, %1, %2;" : "=r"(r) : "r"(saddr), "r"(rank));
    asm volatile("st.shared::cluster.f32 [%0], %1;" :: "r"(r), "f"(v) : "memory");
}
__device__ __forceinline__ void cluster_sync_(){
    asm volatile("barrier.cluster.arrive.aligned;" ::: "memory");
    asm volatile("barrier.cluster.wait.aligned;"   ::: "memory");
}

__global__ __launch_bounds__(256,1) __cluster_dims__(8,1,1)
void lstm_rec_k(const float* __restrict__ W, const int* __restrict__ seq_lens,
                const float* __restrict__ c_in, const float* __restrict__ h_in,
                float* __restrict__ out)
{
    extern __shared__ float sm[];
    float* w_s    = sm + SM_WS;
    float* h_buf  = sm + SM_HBUF;
    float* gate_s = sm + SM_GATE;
    float* c_s    = sm + SM_CS;

    int tid  = threadIdx.x;
    int rank = blockIdx.x & 7;
    int cl   = blockIdx.x >> 3;
    int bb   = (tid >> 4) & 1;
    int col  = (tid & 15) | ((tid >> 5) << 4);    // 0..127
    int bglob = cl*2 + bb;
    int gate = col >> 5, uu0 = col & 31;
    int gcol = gate*256 + rank*32 + uu0;          // global gate column

    const float* Wh = W + (size_t)D_*G4;          // h-part rows 256..511

    // --- one-time: weights into regs (k<KR) packed as f32x2 pairs ---
    unsigned long long wreg2[KR/2];
#pragma unroll
    for (int k2 = 0; k2 < KR/2; k2++){
        float w0 = Wh[(size_t)(2*k2  )*G4 + gcol];
        float w1 = Wh[(size_t)(2*k2+1)*G4 + gcol];
        wreg2[k2] = pk2(w0, w1);
    }
    // rest of weights into smem (only bb==0 threads store)
    if (bb == 0){
        for (int k = KR; k < H_; k++)
            w_s[col*WS_ST + (k - KR)] = Wh[(size_t)k*G4 + gcol];
    }
    // --- init h, c ---
    for (int k = col; k < H_; k += NCOL)
        h_buf[(0*2 + bb)*256 + k] = h_in[(size_t)bglob*H_ + k];
    int slen_u = 0;
    if (tid < 64){
        int b = tid >> 5, uu = tid & 31;
        c_s[b*32 + uu] = c_in[(size_t)(cl*2 + b)*H_ + rank*32 + uu];
        slen_u = seq_lens[cl*2 + b];
    }
    __syncthreads();
    cluster_sync_();

    int phase = 0;
    float pre = g_scr[((size_t)bglob*T_ + 0)*G4 + gcol];

    for (int t = 0; t < T_; t++){
        float pre_nxt = 0.f;
        if (t+1 < T_) pre_nxt = g_scr[((size_t)bglob*T_ + (t+1))*G4 + gcol];

        const float* hb = h_buf + (phase*2 + bb)*256;
        const ulonglong2* hb2 = (const ulonglong2*)hb;
        unsigned long long acc2 = pk2(pre, 0.f);
        // register-weight part
#pragma unroll
        for (int q = 0; q < KR/4; q++){
            ulonglong2 hp = hb2[q];
            fma2(acc2, wreg2[2*q  ], hp.x);
            fma2(acc2, wreg2[2*q+1], hp.y);
        }
        // smem-weight part
        const ulonglong2* w2 = (const ulonglong2*)(w_s + col*WS_ST);
#pragma unroll
        for (int q = 0; q < (H_-KR)/4; q++){
            ulonglong2 hp = hb2[KR/4 + q];
            ulonglong2 wp = w2[q];
            fma2(acc2, wp.x, hp.x);
            fma2(acc2, wp.y, hp.y);
        }
        float2 s = up2(acc2);
        gate_s[bb*NCOL + col] = s.x + s.y;
        __syncthreads();

        if (tid < 64){
            int b = tid >> 5, uu = tid & 31;
            float gi = gate_s[b*NCOL + uu];
            float gj = gate_s[b*NCOL + 32 + uu];
            float gf = gate_s[b*NCOL + 64 + uu];
            float go = gate_s[b*NCOL + 96 + uu];
            float c  = c_s[b*32 + uu];
            float nc = c * sigf(gf + 1.0f) + sigf(gi) * tanhf(gj);
            float nh = tanhf(nc) * sigf(go);
            bool mask = (t < slen_u);
            float h_old = h_buf[(phase*2 + b)*256 + rank*32 + uu];
            float cw = mask ? nc : c;
            float hw = mask ? nh : h_old;
            c_s[b*32 + uu] = cw;
            int bg = cl*2 + b;
            out[LAST_OFF + ((size_t)bg*T_ + t)*H_ + rank*32 + uu] = mask ? nh : 0.f;
            // broadcast new h to all cluster CTAs (phase^1 buffer)
            uint32_t sa = (uint32_t)__cvta_generic_to_shared(
                &h_buf[((phase^1)*2 + b)*256 + rank*32 + uu]);
#pragma unroll
            for (int r2 = 0; r2 < 8; r2++)
                st_cluster_f32(sa, r2, hw);
        }
        cluster_sync_();
        phase ^= 1;
        pre = pre_nxt;
    }

    if (tid < 64){
        int b = tid >> 5, uu = tid & 31;
        int bg = cl*2 + b;
        out[C_OFF  + (size_t)bg*H_ + rank*32 + uu] = c_s[b*32 + uu];
        out[HF_OFF + (size_t)bg*H_ + rank*32 + uu] =
            h_buf[(phase*2 + b)*256 + rank*32 + uu];
    }
}

// ======================================================================
// Kernel 3: logits = last_layer @ W_out + b_out   [65536,256]@[256,18]
// block = 14 rows x 18 outputs = 252 threads
// ======================================================================
#define WO_ST 260

__global__ __launch_bounds__(252) void logits_k(
    const float* __restrict__ Wout, const float* __restrict__ bout,
    float* __restrict__ out)
{
    __shared__ float wo[A_*WO_ST];
    __shared__ float bo[A_];
    int tid = threadIdx.x;
    for (int i = tid; i < H_*A_; i += 252){
        int k = i / A_, a = i % A_;
        wo[a*WO_ST + k] = Wout[(size_t)k*A_ + a];
    }
    if (tid < A_) bo[tid] = bout[tid];
    __syncthreads();

    int r = blockIdx.x*14 + tid/A_;
    int a = tid % A_;
    if (r >= M_) return;
    const float* hrow = out + LAST_OFF + (size_t)r*H_;
    const float* wa = wo + a*WO_ST;
    unsigned long long acc = pk2(0.f, 0.f);
#pragma unroll
    for (int k4 = 0; k4 < H_/4; k4++){
        float4 hv = *(const float4*)&hrow[k4*4];
        float4 wv = *(const float4*)&wa[k4*4];
        fma2(acc, pk2(hv.x,hv.y), pk2(wv.x,wv.y));
        fma2(acc, pk2(hv.z,hv.w), pk2(wv.z,wv.w));
    }
    float2 s = up2(acc);
    out[(size_t)r*A_ + a] = s.x + s.y + bo[a];
}

// ======================================================================
extern "C" void kernel_launch(void* const* d_in, const int* in_sizes, int n_in,
                              void* d_out, int out_size)
{
    const float* x     = (const float*)d_in[0];
    const int*   seq   = (const int*)  d_in[1];
    const float* c_in  = (const float*)d_in[2];
    const float* h_in  = (const float*)d_in[3];
    const float* W     = (const float*)d_in[4];
    const float* b     = (const float*)d_in[5];
    const float* Wout  = (const float*)d_in[6];
    const float* bout  = (const float*)d_in[7];
    float* out = (float*)d_out;

    cudaFuncSetAttribute(lstm_rec_k, cudaFuncAttributeMaxDynamicSharedMemorySize,
                         SMEM_REC_BYTES);

    pregemm_k<<<dim3(G4/PG_BN, M_/PG_BM), 256>>>(x, W, b);
    lstm_rec_k<<<128, 256, SMEM_REC_BYTES>>>(W, seq, c_in, h_in, out);
    logits_k<<<(M_ + 13)/14, 252>>>(Wout, bout, out);
}

// round 5
// speedup vs baseline: 1.2839x; 1.2826x over previous
#include <cuda_runtime.h>
#include <cstdint>

#define B_  32
#define T_  2048
#define D_  256
#define H_  256
#define A_  18
#define G4  1024
#define M_  (B_*T_)          // 65536

#define LOGITS_OFF 0
#define LAST_OFF   ((size_t)M_*A_)                   // 1179648
#define C_OFF      (LAST_OFF + (size_t)M_*H_)        // 17956864
#define HF_OFF     (C_OFF + (size_t)B_*H_)           // 17965056

// 256 MB scratch for pre-computed input gates (x @ Wx + b)
__device__ float g_scr[(size_t)M_ * G4];

// ---------------- f32x2 packed helpers ----------------
__device__ __forceinline__ unsigned long long pk2(float lo, float hi){
    unsigned long long r;
    asm("mov.b64 %0, {%1,%2};" : "=l"(r) : "f"(lo), "f"(hi));
    return r;
}
__device__ __forceinline__ void fma2(unsigned long long &d, unsigned long long a, unsigned long long b){
    asm("fma.rn.f32x2 %0, %1, %2, %0;" : "+l"(d) : "l"(a), "l"(b));
}
__device__ __forceinline__ unsigned long long add2_(unsigned long long a, unsigned long long b){
    unsigned long long r;
    asm("add.rn.f32x2 %0, %1, %2;" : "=l"(r) : "l"(a), "l"(b));
    return r;
}
__device__ __forceinline__ float2 up2(unsigned long long v){
    float2 f;
    asm("mov.b64 {%0,%1}, %2;" : "=f"(f.x), "=f"(f.y) : "l"(v));
    return f;
}

__device__ __forceinline__ float sigf(float x){
    return 1.0f / (1.0f + __expf(-x));
}
__device__ __forceinline__ float tanh_fast(float x){
    return 1.0f - 2.0f / (1.0f + __expf(2.0f * x));
}

// ---------------- mbarrier / DSMEM helpers ----------------
__device__ __forceinline__ void mbar_init(unsigned int a, unsigned int cnt){
    asm volatile("mbarrier.init.shared.b64 [%0], %1;" :: "r"(a), "r"(cnt) : "memory");
}
__device__ __forceinline__ void mbar_expect(unsigned int a, unsigned int tx){
    asm volatile("mbarrier.arrive.expect_tx.shared.b64 _, [%0], %1;" :: "r"(a), "r"(tx) : "memory");
}
__device__ __forceinline__ void mbar_wait(unsigned int a, unsigned int par){
    asm volatile(
        "{\n\t.reg .pred P;\n"
        "LAB_%=:\n\t"
        "mbarrier.try_wait.parity.acquire.cluster.shared::cta.b64 P, [%0], %1, 0x989680;\n\t"
        "@P bra DONE_%=;\n\t"
        "bra LAB_%=;\n"
        "DONE_%=:\n\t}"
        :: "r"(a), "r"(par) : "memory");
}
__device__ __forceinline__ unsigned int mapa_(unsigned int a, unsigned int r){
    unsigned int d;
    asm("mapa.shared::cluster.u32 %0, %1, %2;" : "=r"(d) : "r"(a), "r"(r));
    return d;
}
__device__ __forceinline__ void st_async64(unsigned int dst, unsigned long long v, unsigned int mbar){
    asm volatile("st.async.weak.shared::cluster.mbarrier::complete_tx::bytes.b64 [%0], %1, [%2];"
                 :: "r"(dst), "l"(v), "r"(mbar) : "memory");
}
__device__ __forceinline__ void cluster_sync_(){
    asm volatile("barrier.cluster.arrive.aligned;" ::: "memory");
    asm volatile("barrier.cluster.wait.aligned;"   ::: "memory");
}

// ======================================================================
// Kernel 1: pre-GEMM  G[m][c] = x[m,:] @ W[0:256, c] + b[c]
// BM=128, BN=128, BK=16, 256 threads, thread tile 8x8 (two 4-col halves)
// ======================================================================
#define PG_BM 128
#define PG_BN 128
#define PG_BK 16

__global__ __launch_bounds__(256,2) void pregemm_k(
    const float* __restrict__ x, const float* __restrict__ W,
    const float* __restrict__ bias)
{
    __shared__ float a_s[PG_BK][PG_BM];
    __shared__ float b_s[PG_BK][PG_BN];

    int tid = threadIdx.x;
    int m0 = blockIdx.y * PG_BM;
    int n0 = blockIdx.x * PG_BN;
    int tx = tid & 15;           // col group: cols tx*4 and 64+tx*4
    int ty = tid >> 4;           // row group: rows ty*8..+7

    unsigned long long acc[8][4];
#pragma unroll
    for (int i = 0; i < 8; i++)
#pragma unroll
        for (int j = 0; j < 4; j++) acc[i][j] = 0ull;

    for (int k0 = 0; k0 < D_; k0 += PG_BK){
        // A tile: 128 rows x 16 k = 512 float4, 2 per thread
#pragma unroll
        for (int i = 0; i < 2; i++){
            int f4 = tid*2 + i;
            int m  = f4 >> 2;
            int kq = f4 & 3;
            float4 v = *(const float4*)&x[(size_t)(m0+m)*D_ + k0 + kq*4];
            a_s[kq*4+0][m] = v.x; a_s[kq*4+1][m] = v.y;
            a_s[kq*4+2][m] = v.z; a_s[kq*4+3][m] = v.w;
        }
        // B tile: 16 rows x 128 cols = 512 float4, 2 per thread
#pragma unroll
        for (int i = 0; i < 2; i++){
            int f4 = tid*2 + i;
            int row = f4 >> 5, cq = f4 & 31;
            float4 v = *(const float4*)&W[(size_t)(k0+row)*G4 + n0 + cq*4];
            *(float4*)&b_s[row][cq*4] = v;
        }
        __syncthreads();
#pragma unroll
        for (int kk = 0; kk < PG_BK; kk++){
            float4 a0 = *(float4*)&a_s[kk][ty*8];
            float4 a1 = *(float4*)&a_s[kk][ty*8+4];
            float4 b0 = *(float4*)&b_s[kk][tx*4];
            float4 b1 = *(float4*)&b_s[kk][64 + tx*4];
            unsigned long long bp0 = pk2(b0.x,b0.y), bp1 = pk2(b0.z,b0.w);
            unsigned long long bp2 = pk2(b1.x,b1.y), bp3 = pk2(b1.z,b1.w);
            float ar[8] = {a0.x,a0.y,a0.z,a0.w,a1.x,a1.y,a1.z,a1.w};
#pragma unroll
            for (int i = 0; i < 8; i++){
                unsigned long long ap = pk2(ar[i], ar[i]);
                fma2(acc[i][0], ap, bp0);
                fma2(acc[i][1], ap, bp1);
                fma2(acc[i][2], ap, bp2);
                fma2(acc[i][3], ap, bp3);
            }
        }
        __syncthreads();
    }

    float4 bv0 = *(const float4*)&bias[n0 + tx*4];
    float4 bv1 = *(const float4*)&bias[n0 + 64 + tx*4];
#pragma unroll
    for (int i = 0; i < 8; i++){
        float2 l0 = up2(acc[i][0]), h0 = up2(acc[i][1]);
        float2 l1 = up2(acc[i][2]), h1 = up2(acc[i][3]);
        size_t row = (size_t)(m0 + ty*8 + i)*G4;
        *(float4*)&g_scr[row + n0 + tx*4] =
            make_float4(l0.x+bv0.x, l0.y+bv0.y, h0.x+bv0.z, h0.y+bv0.w);
        *(float4*)&g_scr[row + n0 + 64 + tx*4] =
            make_float4(l1.x+bv1.x, l1.y+bv1.y, h1.x+bv1.z, h1.y+bv1.w);
    }
}

// ======================================================================
// Kernel 2: recurrent LSTM.
// 16 clusters x 8 CTAs. Cluster = 2 batches. CTA = 32 units.
// 256 threads = 8 warps; warp = 4 units (u_lo) x 8 k-chunks (kq).
// Thread: all 4 gates x 32 k in registers, both batches accumulated.
// Shuffle-butterfly reduce distributes 8 (batch,gate) combos onto kq lanes.
// h exchanged via st.async + mbarrier complete_tx (double-buffered).
// ======================================================================
#define HPAD 288   // 256 + 4-float pad per 32 => conflict-free chunk loads

__global__ __launch_bounds__(256,1) __cluster_dims__(8,1,1)
void lstm_rec_k(const float* __restrict__ W, const int* __restrict__ seq_lens,
                const float* __restrict__ c_in, const float* __restrict__ h_in,
                float* __restrict__ out)
{
    __shared__ __align__(16) float h_s[2][2][HPAD];     // [phase][batch][padded k]
    __shared__ __align__(8) unsigned long long barr[2];

    int tid  = threadIdx.x;
    int warp = tid >> 5, lane = tid & 31;
    int rank = blockIdx.x & 7, cl = blockIdx.x >> 3;
    int u_lo = lane >> 3;           // 0..3
    int kq   = lane & 7;            // 0..7  (k-chunk / reduction lane)
    int b_c  = kq >> 2;             // this lane's combo batch
    int g_c  = kq & 3;              // this lane's combo gate
    int u    = rank*32 + warp*4 + u_lo;     // global unit 0..255
    int bg_c = cl*2 + b_c;                  // combo's global batch
    int gcol_c = g_c*256 + u;               // combo's global gate column

    // --- weights: 4 gates x 32 k (chunk kq) in 64 u64 registers ---
    const float* Wh = W + (size_t)D_*G4;
    unsigned long long wreg[4][16];
#pragma unroll
    for (int g = 0; g < 4; g++){
        int gc = g*256 + u;
#pragma unroll
        for (int j = 0; j < 16; j++){
            int k = kq*32 + 2*j;
            wreg[g][j] = pk2(Wh[(size_t)k*G4 + gc], Wh[(size_t)(k+1)*G4 + gc]);
        }
    }

    unsigned int hsm = (unsigned int)__cvta_generic_to_shared(&h_s[0][0][0]);
    unsigned int bar_lo = (unsigned int)__cvta_generic_to_shared(&barr[0]);
    int bar_delta = (int)(bar_lo - hsm);

    unsigned int hdst[8];
#pragma unroll
    for (int r = 0; r < 8; r++) hdst[r] = mapa_(hsm, (unsigned)r);

    if (tid == 0){
        mbar_init(bar_lo,     1);
        mbar_init(bar_lo + 8, 1);
        mbar_expect(bar_lo,     2048);   // init-h traffic (phase-0 buffer)
        mbar_expect(bar_lo + 8, 2048);   // step-0 writers (phase-1 buffer)
    }
    __syncthreads();
    cluster_sync_();   // barriers armed cluster-wide before any st.async

    // writers: g_c == 0 lanes own combo (b_c, unit u); is_wr2 packs pairs
    bool is_wr  = (g_c == 0);
    bool is_wr2 = is_wr && ((u_lo & 1) == 0);
    float c_r = 0.f, h_r = 0.f; int slen = 0;
    if (is_wr){
        c_r  = c_in[(size_t)bg_c*H_ + u];
        h_r  = h_in[(size_t)bg_c*H_ + u];
        slen = seq_lens[bg_c];
    }

    // padded element offset (bytes) for unit u within an h row
    int upos = (u + ((u >> 5) << 2)) * 4;

    // --- initial h broadcast into phase-0 buffer ---
    {
        float h_hi = __shfl_down_sync(0xffffffffu, h_r, 8);
        if (is_wr2){
            unsigned long long v = pk2(h_r, h_hi);
            int off = (0*2 + b_c)*HPAD*4 + upos;
#pragma unroll
            for (int r = 0; r < 8; r++)
                st_async64(hdst[r] + off, v, hdst[r] + bar_delta + 0);
        }
    }

    float pre = g_scr[((size_t)bg_c*T_ + 0)*G4 + gcol_c];

    for (int t = 0; t < T_; t++){
        int p   = t & 1;
        int par = (t >> 1) & 1;
        mbar_wait(bar_lo + p*8, (unsigned)par);
        if (tid == 0) mbar_expect(bar_lo + p*8, 2048);   // re-arm for t+2

        // prefetch next step's pre-gate (independent of fma loop)
        int tn = (t+1 < T_) ? t+1 : t;
        float pre_n = g_scr[((size_t)bg_c*T_ + tn)*G4 + gcol_c];

        // --- gemm: acc[g][b] over this thread's 32-k chunk ---
        const ulonglong2* h0 = (const ulonglong2*)&h_s[p][0][kq*36];
        const ulonglong2* h1 = (const ulonglong2*)&h_s[p][1][kq*36];
        unsigned long long acc[4][2];
#pragma unroll
        for (int g = 0; g < 4; g++){ acc[g][0] = 0ull; acc[g][1] = 0ull; }
#pragma unroll
        for (int q = 0; q < 8; q++){
            ulonglong2 hb0 = h0[q];
            ulonglong2 hb1 = h1[q];
#pragma unroll
            for (int g = 0; g < 4; g++){
                fma2(acc[g][0], wreg[g][2*q  ], hb0.x);
                fma2(acc[g][0], wreg[g][2*q+1], hb0.y);
                fma2(acc[g][1], wreg[g][2*q  ], hb1.x);
                fma2(acc[g][1], wreg[g][2*q+1], hb1.y);
            }
        }

        // --- butterfly reduce over kq; lane ends with combo (b_c, g_c) ---
        unsigned long long acck[4];
#pragma unroll
        for (int g = 0; g < 4; g++){
            unsigned long long send = acc[g][b_c ^ 1];
            unsigned long long got  = __shfl_xor_sync(0xffffffffu, send, 4);
            acck[g] = add2_(acc[g][b_c], got);
        }
        int gh = (kq >> 1) & 1;
        unsigned long long s0 = acck[2*(gh^1)    ];
        unsigned long long s1 = acck[2*(gh^1) + 1];
        unsigned long long r0 = __shfl_xor_sync(0xffffffffu, s0, 2);
        unsigned long long r1 = __shfl_xor_sync(0xffffffffu, s1, 2);
        unsigned long long accg0 = add2_(acck[2*gh    ], r0);
        unsigned long long accg1 = add2_(acck[2*gh + 1], r1);
        int gl = kq & 1;
        unsigned long long s2 = gl ? accg0 : accg1;
        unsigned long long r2 = __shfl_xor_sync(0xffffffffu, s2, 1);
        unsigned long long fin = add2_(gl ? accg1 : accg0, r2);
        float2 fv = up2(fin);
        float s_val = fv.x + fv.y + pre;     // pre lands on its own combo lane

        // --- gather 4 gates for (u_lo, b_c) ---
        int base = (lane & 24) | (b_c << 2);
        float gi = __shfl_sync(0xffffffffu, s_val, base + 0);
        float gj = __shfl_sync(0xffffffffu, s_val, base + 1);
        float gf = __shfl_sync(0xffffffffu, s_val, base + 2);
        float go = __shfl_sync(0xffffffffu, s_val, base + 3);

        // --- activation (meaningful on writer lanes) ---
        float sf = sigf(gf + 1.0f);
        float si = sigf(gi);
        float tj = tanh_fast(gj);
        float so = sigf(go);
        float nc = c_r * sf + si * tj;
        float nh = tanh_fast(nc) * so;
        bool mask = (t < slen);
        if (mask){ c_r = nc; h_r = nh; }
        float oval = mask ? nh : 0.f;

        // --- pack pairs (u, u+1) and emit ---
        float o_hi = __shfl_down_sync(0xffffffffu, oval, 8);
        float h_hi = __shfl_down_sync(0xffffffffu, h_r,  8);
        if (is_wr2){
            *(float2*)&out[LAST_OFF + ((size_t)bg_c*T_ + t)*H_ + u] =
                make_float2(oval, o_hi);
            if (t + 1 < T_){
                unsigned long long hv = pk2(h_r, h_hi);
                int off  = ((p^1)*2 + b_c)*HPAD*4 + upos;
                int boff = bar_delta + (p^1)*8;
#pragma unroll
                for (int r = 0; r < 8; r++)
                    st_async64(hdst[r] + off, hv, hdst[r] + boff);
            }
        }
        pre = pre_n;
    }

    if (is_wr){
        out[C_OFF  + (size_t)bg_c*H_ + u] = c_r;
        out[HF_OFF + (size_t)bg_c*H_ + u] = h_r;
    }
    cluster_sync_();   // no CTA exits while peers may still target its smem
}

// ======================================================================
// Kernel 3: logits = last_layer @ W_out + b_out   [65536,256]@[256,18]
// block = 14 rows x 18 outputs = 252 threads
// ======================================================================
#define WO_ST 260

__global__ __launch_bounds__(252) void logits_k(
    const float* __restrict__ Wout, const float* __restrict__ bout,
    float* __restrict__ out)
{
    __shared__ float wo[A_*WO_ST];
    __shared__ float bo[A_];
    int tid = threadIdx.x;
    for (int i = tid; i < H_*A_; i += 252){
        int k = i / A_, a = i % A_;
        wo[a*WO_ST + k] = Wout[(size_t)k*A_ + a];
    }
    if (tid < A_) bo[tid] = bout[tid];
    __syncthreads();

    int r = blockIdx.x*14 + tid/A_;
    int a = tid % A_;
    if (r >= M_) return;
    const float* hrow = out + LAST_OFF + (size_t)r*H_;
    const float* wa = wo + a*WO_ST;
    unsigned long long acc = 0ull;
#pragma unroll
    for (int k4 = 0; k4 < H_/4; k4++){
        float4 hv = *(const float4*)&hrow[k4*4];
        float4 wv = *(const float4*)&wa[k4*4];
        fma2(acc, pk2(hv.x,hv.y), pk2(wv.x,wv.y));
        fma2(acc, pk2(hv.z,hv.w), pk2(wv.z,wv.w));
    }
    float2 s = up2(acc);
    out[(size_t)r*A_ + a] = s.x + s.y + bo[a];
}

// ======================================================================
extern "C" void kernel_launch(void* const* d_in, const int* in_sizes, int n_in,
                              void* d_out, int out_size)
{
    const float* x     = (const float*)d_in[0];
    const int*   seq   = (const int*)  d_in[1];
    const float* c_in  = (const float*)d_in[2];
    const float* h_in  = (const float*)d_in[3];
    const float* W     = (const float*)d_in[4];
    const float* b     = (const float*)d_in[5];
    const float* Wout  = (const float*)d_in[6];
    const float* bout  = (const float*)d_in[7];
    float* out = (float*)d_out;

    pregemm_k<<<dim3(G4/PG_BN, M_/PG_BM), 256>>>(x, W, b);
    lstm_rec_k<<<128, 256>>>(W, seq, c_in, h_in, out);
    logits_k<<<(M_ + 13)/14, 252>>>(Wout, bout, out);
}